// round 17
// baseline (speedup 1.0000x reference)
#include <cuda_runtime.h>
#include <cuda_fp16.h>
#include <math.h>
#include <stdint.h>

#define Nn   50000
#define Ee   800000
#define INC  128
#define Hd   256
#define Gg   128
#define NEG  0.2f
#define SCB  512
#define NSB  ((Nn + SCB - 1) / SCB)
#define HROW 25088                        // row-half boundary (196 tiles * 128)

// ---------------- scratch (device globals; no allocations allowed) ----------
__device__ float  g_xp[(size_t)Nn * Hd];
__device__ __half g_xp16[(size_t)Nn * Hd];
__device__ float g_ssrc0[Nn], g_sdst0[Nn];
__device__ float g_ssrc1[Nn], g_sdst1[Nn];
__device__ float g_p[Ee];
__device__ int   g_src[Ee];
__device__ int   g_dst[Ee];
__device__ int   g_batch[Nn];
__device__ int   g_cnt[Nn];
__device__ int   g_cur[Nn];
__device__ int   g_offs[Nn + 1];
__device__ int   g_bsum[NSB];
__device__ int   g_boff[NSB];
__device__ int   g_adj[Ee];
__device__ int   g_adjd[Ee];
__device__ int   g_gstart[Gg + 1];
__device__ int   g_is64;
__device__ __half g_ah[(size_t)Nn * Hd];
__device__ __half g_bt0h[256 * 128];
__device__ __half g_bt1h[256 * 256];
__device__ __half g_bihh[768 * 256];

// ---------------------------- PTX helpers -----------------------------------
__device__ __forceinline__ uint32_t smem_u32(const void* p) {
    uint32_t a;
    asm("{ .reg .u64 t; cvta.to.shared.u64 t, %1; cvt.u32.u64 %0, t; }" : "=r"(a) : "l"(p));
    return a;
}
__device__ __forceinline__ void ldsm4(uint32_t& r0, uint32_t& r1, uint32_t& r2, uint32_t& r3,
                                      uint32_t addr) {
    asm volatile("ldmatrix.sync.aligned.m8n8.x4.shared.b16 {%0,%1,%2,%3}, [%4];"
                 : "=r"(r0), "=r"(r1), "=r"(r2), "=r"(r3) : "r"(addr));
}
__device__ __forceinline__ void mma16816(float* d, const uint32_t* a, const uint32_t* b) {
    asm volatile("mma.sync.aligned.m16n8k16.row.col.f32.f16.f16.f32 "
                 "{%0,%1,%2,%3}, {%4,%5,%6,%7}, {%8,%9}, {%0,%1,%2,%3};"
                 : "+f"(d[0]), "+f"(d[1]), "+f"(d[2]), "+f"(d[3])
                 : "r"(a[0]), "r"(a[1]), "r"(a[2]), "r"(a[3]), "r"(b[0]), "r"(b[1]));
}
__device__ __forceinline__ void cpa16(uint32_t dst, const void* src, uint32_t sz) {
    asm volatile("cp.async.cg.shared.global [%0], [%1], 16, %2;"
                 :: "r"(dst), "l"(src), "r"(sz) : "memory");
}
__device__ __forceinline__ void cpa_commit() {
    asm volatile("cp.async.commit_group;" ::: "memory");
}
template<int N> __device__ __forceinline__ void cpa_wait() {
    asm volatile("cp.async.wait_group %0;" :: "n"(N) : "memory");
}

// ---------------- index dtype detection + decode ----------------------------
__global__ void k_detect(const int* __restrict__ ei32)
{
    int lane = threadIdx.x;
    int bad = (ei32[2 * lane + 1] != 0) | (ei32[2 * (lane + 32) + 1] != 0);
    unsigned m = __ballot_sync(0xffffffffu, bad);
    if (lane == 0) g_is64 = (m == 0u);
}
__global__ void k_decode_batch(const int* __restrict__ b32)
{
    int n = blockIdx.x * blockDim.x + threadIdx.x;
    if (n >= Nn) return;
    g_batch[n] = g_is64 ? b32[2 * n] : b32[n];
    g_cnt[n] = 0;  g_cur[n] = 0;
}
__global__ void k_decode_count(const int* __restrict__ ei32)
{
    int e = blockIdx.x * blockDim.x + threadIdx.x;
    if (e >= Ee) return;
    int s, d;
    if (g_is64) { s = ei32[2 * e]; d = ei32[2 * (Ee + e)]; }
    else        { s = ei32[e];     d = ei32[Ee + e]; }
    g_src[e] = s;
    g_dst[e] = d;
    atomicAdd(&g_cnt[d], 1);
}

// ------- weight prep: transpose + fp16; also zeros attention scratch --------
__global__ void k_prep_w(const float* __restrict__ W0, const float* __restrict__ W1,
                         const float* __restrict__ Wih)
{
    int t = blockIdx.x * blockDim.x + threadIdx.x;
    if (t < Nn) {
        g_ssrc0[t] = 0.f; g_sdst0[t] = 0.f;
        g_ssrc1[t] = 0.f; g_sdst1[t] = 0.f;
    }
    if (t < 256 * 128) {
        int n = t >> 7, k = t & 127;
        g_bt0h[t] = __float2half_rn(W0[k * 256 + n]);
    }
    if (t < 256 * 256) {
        int n = t >> 8, k = t & 255;
        g_bt1h[t] = __float2half_rn(W1[k * 256 + n]);
    }
    if (t < 768 * 256) {
        g_bihh[t] = __float2half_rn(Wih[t]);
    }
}

// ---------------- A convert for x: fp32 -> fp16 -------------------------------
__global__ __launch_bounds__(256) void k_split_x(const float* __restrict__ src, int n4)
{
    int t = blockIdx.x * blockDim.x + threadIdx.x;
    if (t >= n4) return;
    float4 v = ((const float4*)src)[t];
    ushort4 hs;
    hs.x = __half_as_ushort(__float2half_rn(v.x));
    hs.y = __half_as_ushort(__float2half_rn(v.y));
    hs.z = __half_as_ushort(__float2half_rn(v.z));
    hs.w = __half_as_ushort(__float2half_rn(v.w));
    ((ushort4*)g_ah)[t] = hs;
}

// -------- pipelined 1-term fp16 GEMM + attention-dot epilogue ----------------
#define SSTRIDE 40
#define ABYTES  (128 * SSTRIDE * 2)
#define BUF1    (2 * ABYTES)
__global__ __launch_bounds__(256, 2) void k_mm_f16(const __half* __restrict__ AH,
                                                   const __half* __restrict__ BtH,
                                                   __half* __restrict__ C16,
                                                   const float* __restrict__ avs,
                                                   const float* __restrict__ avd,
                                                   float* __restrict__ ssrc,
                                                   float* __restrict__ sdst,
                                                   int M, int Nc, int K, int rbase)
{
    extern __shared__ char smem[];
    const uint32_t sb = smem_u32(smem);

    const int tid  = threadIdx.x;
    const int wid  = tid >> 5, lane = tid & 31;
    const int wm   = wid & 1, wn = wid >> 1;
    const int row0 = rbase + blockIdx.y * 128, col0 = blockIdx.x * 128;

    uint32_t aoff[4];
    #pragma unroll
    for (int mi = 0; mi < 4; mi++) {
        int r = wm * 64 + mi * 16 + (lane & 7) + ((lane >> 3) & 1) * 8;
        aoff[mi] = (uint32_t)(r * (SSTRIDE * 2) + (lane >> 4) * 16);
    }
    uint32_t boff[2];
    #pragma unroll
    for (int jp = 0; jp < 2; jp++) {
        int n = wn * 32 + jp * 16 + (lane & 7) + ((lane >> 4) & 1) * 8;
        boff[jp] = (uint32_t)(n * (SSTRIDE * 2) + ((lane >> 3) & 1) * 16);
    }

    float acc[4][4][4];
    #pragma unroll
    for (int i = 0; i < 4; i++)
        #pragma unroll
        for (int j = 0; j < 4; j++)
            #pragma unroll
            for (int q = 0; q < 4; q++) acc[i][j][q] = 0.f;

    const int nit = K >> 5;
    auto issue = [&](int kt, int p) {
        #pragma unroll
        for (int c = 0; c < 2; c++) {
            int lin = tid + c * 256;
            int row = lin >> 2, q = lin & 3;
            uint32_t sd = sb + (uint32_t)(p * BUF1 + row * (SSTRIDE * 2) + q * 16);
            int ar = row0 + row;
            uint32_t asz = (ar < M) ? 16u : 0u;
            if (ar >= M) ar = 0;
            size_t aoffg = (size_t)ar * K + kt * 32 + q * 8;
            size_t boffg = (size_t)(col0 + row) * K + kt * 32 + q * 8;
            cpa16(sd,          AH + aoffg, asz);
            cpa16(sd + ABYTES, BtH + boffg, 16u);
        }
        cpa_commit();
    };

    issue(0, 0);
    for (int kt = 0; kt < nit; kt++) {
        const int p = kt & 1;
        if (kt + 1 < nit) { issue(kt + 1, p ^ 1); cpa_wait<1>(); }
        else              { cpa_wait<0>(); }
        __syncthreads();

        const uint32_t uAh = sb + p * BUF1;
        const uint32_t uBh = uAh + ABYTES;

        #pragma unroll
        for (int ks = 0; ks < 2; ks++) {
            const uint32_t kb = (uint32_t)(ks * 32);
            uint32_t ah[4][4], bf[4][2];
            #pragma unroll
            for (int mi = 0; mi < 4; mi++)
                ldsm4(ah[mi][0], ah[mi][1], ah[mi][2], ah[mi][3], uAh + aoff[mi] + kb);
            #pragma unroll
            for (int jp = 0; jp < 2; jp++)
                ldsm4(bf[jp * 2][0], bf[jp * 2][1], bf[jp * 2 + 1][0], bf[jp * 2 + 1][1],
                      uBh + boff[jp] + kb);
            #pragma unroll
            for (int mi = 0; mi < 4; mi++)
                #pragma unroll
                for (int nj = 0; nj < 4; nj++)
                    mma16816(acc[mi][nj], ah[mi], bf[nj]);
        }
        __syncthreads();
    }

    float as0[4], as1[4], ad0[4], ad1[4];
    #pragma unroll
    for (int nj = 0; nj < 4; nj++) {
        int c = col0 + wn * 32 + (lane & 3) * 2 + nj * 8;
        as0[nj] = avs[c]; as1[nj] = avs[c + 1];
        ad0[nj] = avd[c]; ad1[nj] = avd[c + 1];
    }

    #pragma unroll
    for (int mi = 0; mi < 4; mi++) {
        int r0g = row0 + wm * 64 + mi * 16 + (lane >> 2);
        int cg  = col0 + wn * 32 + (lane & 3) * 2;
        float pss0 = 0.f, psd0 = 0.f, pss1 = 0.f, psd1 = 0.f;
        #pragma unroll
        for (int nj = 0; nj < 4; nj++) {
            int c = cg + nj * 8;
            if (r0g < M)
                *(__half2*)(C16 + (size_t)r0g * Nc + c) =
                    __floats2half2_rn(acc[mi][nj][0], acc[mi][nj][1]);
            if (r0g + 8 < M)
                *(__half2*)(C16 + (size_t)(r0g + 8) * Nc + c) =
                    __floats2half2_rn(acc[mi][nj][2], acc[mi][nj][3]);
            pss0 = fmaf(acc[mi][nj][0], as0[nj], fmaf(acc[mi][nj][1], as1[nj], pss0));
            psd0 = fmaf(acc[mi][nj][0], ad0[nj], fmaf(acc[mi][nj][1], ad1[nj], psd0));
            pss1 = fmaf(acc[mi][nj][2], as0[nj], fmaf(acc[mi][nj][3], as1[nj], pss1));
            psd1 = fmaf(acc[mi][nj][2], ad0[nj], fmaf(acc[mi][nj][3], ad1[nj], psd1));
        }
        pss0 += __shfl_xor_sync(0xffffffffu, pss0, 1);
        pss0 += __shfl_xor_sync(0xffffffffu, pss0, 2);
        psd0 += __shfl_xor_sync(0xffffffffu, psd0, 1);
        psd0 += __shfl_xor_sync(0xffffffffu, psd0, 2);
        pss1 += __shfl_xor_sync(0xffffffffu, pss1, 1);
        pss1 += __shfl_xor_sync(0xffffffffu, pss1, 2);
        psd1 += __shfl_xor_sync(0xffffffffu, psd1, 1);
        psd1 += __shfl_xor_sync(0xffffffffu, psd1, 2);
        if ((lane & 3) == 0) {
            if (r0g < M) {
                atomicAdd(&ssrc[r0g], pss0);
                atomicAdd(&sdst[r0g], psd0);
            }
            if (r0g + 8 < M) {
                atomicAdd(&ssrc[r0g + 8], pss1);
                atomicAdd(&sdst[r0g + 8], psd1);
            }
        }
    }
}

// -------- fused GRU GEMM: flattened 24-chunk pipeline, fp16 stash, 2 CTA/SM --
#define STSTR  130
__global__ __launch_bounds__(256, 2) void k_mm_gru(const __half* __restrict__ AH,
                                                   const __half* __restrict__ BtH,
                                                   const float* __restrict__ b_ih,
                                                   const float* __restrict__ b_hh,
                                                   float* __restrict__ OUT,
                                                   int M, int rbase)
{
    extern __shared__ char smem[];
    const uint32_t sb = smem_u32(smem);
    __half* stash_r = (__half*)(smem + 2 * BUF1);
    __half* stash_z = stash_r + 128 * STSTR;

    const int tid  = threadIdx.x;
    const int wid  = tid >> 5, lane = tid & 31;
    const int wm   = wid & 1, wn = wid >> 1;
    const int row0 = rbase + blockIdx.y * 128, col0 = blockIdx.x * 128;
    const int K = Hd;
    const int NCH = 3 * (K >> 5);

    uint32_t aoff[4];
    #pragma unroll
    for (int mi = 0; mi < 4; mi++) {
        int r = wm * 64 + mi * 16 + (lane & 7) + ((lane >> 3) & 1) * 8;
        aoff[mi] = (uint32_t)(r * (SSTRIDE * 2) + (lane >> 4) * 16);
    }
    uint32_t boff[2];
    #pragma unroll
    for (int jp = 0; jp < 2; jp++) {
        int n = wn * 32 + jp * 16 + (lane & 7) + ((lane >> 4) & 1) * 8;
        boff[jp] = (uint32_t)(n * (SSTRIDE * 2) + ((lane >> 3) & 1) * 16);
    }

    auto issue = [&](int tt, int p) {
        const int gate = tt >> 3, kt = tt & 7;
        const int brow0 = gate * 256 + col0;
        #pragma unroll
        for (int c = 0; c < 2; c++) {
            int lin = tid + c * 256;
            int row = lin >> 2, q = lin & 3;
            uint32_t sd = sb + (uint32_t)(p * BUF1 + row * (SSTRIDE * 2) + q * 16);
            int ar = row0 + row;
            uint32_t asz = (ar < M) ? 16u : 0u;
            if (ar >= M) ar = 0;
            size_t aoffg = (size_t)ar * K + kt * 32 + q * 8;
            size_t boffg = (size_t)(brow0 + row) * K + kt * 32 + q * 8;
            cpa16(sd,          AH + aoffg, asz);
            cpa16(sd + ABYTES, BtH + boffg, 16u);
        }
        cpa_commit();
    };

    float acc[4][4][4];
    #pragma unroll
    for (int i = 0; i < 4; i++)
        #pragma unroll
        for (int j = 0; j < 4; j++)
            #pragma unroll
            for (int q = 0; q < 4; q++) acc[i][j][q] = 0.f;

    issue(0, 0);
    for (int tt = 0; tt < NCH; tt++) {
        const int p = tt & 1;
        if (tt + 1 < NCH) { issue(tt + 1, p ^ 1); cpa_wait<1>(); }
        else              { cpa_wait<0>(); }
        __syncthreads();

        const uint32_t uAh = sb + p * BUF1;
        const uint32_t uBh = uAh + ABYTES;

        #pragma unroll
        for (int ks = 0; ks < 2; ks++) {
            const uint32_t kb = (uint32_t)(ks * 32);
            uint32_t ah[4][4], bf[4][2];
            #pragma unroll
            for (int mi = 0; mi < 4; mi++)
                ldsm4(ah[mi][0], ah[mi][1], ah[mi][2], ah[mi][3], uAh + aoff[mi] + kb);
            #pragma unroll
            for (int jp = 0; jp < 2; jp++)
                ldsm4(bf[jp * 2][0], bf[jp * 2][1], bf[jp * 2 + 1][0], bf[jp * 2 + 1][1],
                      uBh + boff[jp] + kb);
            #pragma unroll
            for (int mi = 0; mi < 4; mi++)
                #pragma unroll
                for (int nj = 0; nj < 4; nj++)
                    mma16816(acc[mi][nj], ah[mi], bf[nj]);
        }
        __syncthreads();

        if ((tt & 7) == 7) {
            const int gate = tt >> 3;
            if (gate < 2) {
                __half* st = (gate == 0) ? stash_r : stash_z;
                const int go = gate * 256 + col0;
                #pragma unroll
                for (int mi = 0; mi < 4; mi++) {
                    int rl = wm * 64 + mi * 16 + (lane >> 2);
                    #pragma unroll
                    for (int nj = 0; nj < 4; nj++) {
                        int cl = wn * 32 + (lane & 3) * 2 + nj * 8;
                        float bs0 = b_ih[go + cl]     + b_hh[go + cl];
                        float bs1 = b_ih[go + cl + 1] + b_hh[go + cl + 1];
                        float s00 = 1.f / (1.f + expf(-(acc[mi][nj][0] + bs0)));
                        float s01 = 1.f / (1.f + expf(-(acc[mi][nj][1] + bs1)));
                        float s10 = 1.f / (1.f + expf(-(acc[mi][nj][2] + bs0)));
                        float s11 = 1.f / (1.f + expf(-(acc[mi][nj][3] + bs1)));
                        *(__half2*)&st[rl * STSTR + cl]       = __floats2half2_rn(s00, s01);
                        *(__half2*)&st[(rl + 8) * STSTR + cl] = __floats2half2_rn(s10, s11);
                    }
                }
            } else {
                const int go = 512 + col0;
                #pragma unroll
                for (int mi = 0; mi < 4; mi++) {
                    int rl = wm * 64 + mi * 16 + (lane >> 2);
                    int gr0 = row0 + rl, gr1 = gr0 + 8;
                    #pragma unroll
                    for (int nj = 0; nj < 4; nj++) {
                        int cl = wn * 32 + (lane & 3) * 2 + nj * 8;
                        float bi0 = b_ih[go + cl],     bh0 = b_hh[go + cl];
                        float bi1 = b_ih[go + cl + 1], bh1 = b_hh[go + cl + 1];
                        {
                            float2 rr = __half22float2(*(__half2*)&stash_r[rl * STSTR + cl]);
                            float2 zz = __half22float2(*(__half2*)&stash_z[rl * STSTR + cl]);
                            float h0 = (1.f - zz.x) * tanhf(acc[mi][nj][0] + bi0 + rr.x * bh0);
                            float h1 = (1.f - zz.y) * tanhf(acc[mi][nj][1] + bi1 + rr.y * bh1);
                            if (gr0 < M)
                                *(float2*)(OUT + (size_t)gr0 * Hd + col0 + cl) = make_float2(h0, h1);
                        }
                        {
                            float2 rr = __half22float2(*(__half2*)&stash_r[(rl + 8) * STSTR + cl]);
                            float2 zz = __half22float2(*(__half2*)&stash_z[(rl + 8) * STSTR + cl]);
                            float h0 = (1.f - zz.x) * tanhf(acc[mi][nj][2] + bi0 + rr.x * bh0);
                            float h1 = (1.f - zz.y) * tanhf(acc[mi][nj][3] + bi1 + rr.y * bh1);
                            if (gr1 < M)
                                *(float2*)(OUT + (size_t)gr1 * Hd + col0 + cl) = make_float2(h0, h1);
                        }
                    }
                }
            }
            #pragma unroll
            for (int i = 0; i < 4; i++)
                #pragma unroll
                for (int j = 0; j < 4; j++)
                    #pragma unroll
                    for (int q = 0; q < 4; q++) acc[i][j][q] = 0.f;
        }
    }
}

// ------------------------- device-wide 3-phase scan --------------------------
__global__ __launch_bounds__(SCB) void k_scan_a(void)
{
    __shared__ int ssum[SCB];
    int i = blockIdx.x * SCB + threadIdx.x;
    int v = (i < Nn) ? g_cnt[i] : 0;
    ssum[threadIdx.x] = v;
    __syncthreads();
    #pragma unroll
    for (int off = 1; off < SCB; off <<= 1) {
        int t = (threadIdx.x >= off) ? ssum[threadIdx.x - off] : 0;
        __syncthreads();
        ssum[threadIdx.x] += t;
        __syncthreads();
    }
    if (i < Nn) g_offs[i] = ssum[threadIdx.x] - v;
    if (threadIdx.x == SCB - 1) g_bsum[blockIdx.x] = ssum[SCB - 1];
}
__global__ __launch_bounds__(128) void k_scan_b(void)
{
    __shared__ int ssum[128];
    int t = threadIdx.x;
    int v = (t < NSB) ? g_bsum[t] : 0;
    ssum[t] = v;
    __syncthreads();
    #pragma unroll
    for (int off = 1; off < 128; off <<= 1) {
        int u = (t >= off) ? ssum[t - off] : 0;
        __syncthreads();
        ssum[t] += u;
        __syncthreads();
    }
    if (t < NSB) g_boff[t] = ssum[t] - v;
}
__global__ __launch_bounds__(SCB) void k_scan_c(void)
{
    int i = blockIdx.x * SCB + threadIdx.x;
    if (i < Nn) g_offs[i] += g_boff[blockIdx.x];
    if (i == 0) g_offs[Nn] = Ee;
}
__global__ void k_fill(void)
{
    int e = blockIdx.x * blockDim.x + threadIdx.x;
    if (e >= Ee) return;
    int d = g_dst[e];
    int pos = atomicAdd(&g_cur[d], 1);
    int slot = g_offs[d] + pos;
    g_adj[slot]  = g_src[e];
    g_adjd[slot] = d;
}

// ---- edge weights: p[i] = exp(lrelu(ssrc[src]+sdst[dst])) (pure map) --------
__global__ __launch_bounds__(256) void k_edgep(const float* __restrict__ ssrc,
                                               const float* __restrict__ sdst)
{
    int i = blockIdx.x * blockDim.x + threadIdx.x;
    if (i >= Ee) return;
    float v = ssrc[g_adj[i]] + sdst[g_adjd[i]];
    v = v > 0.f ? v : NEG * v;
    g_p[i] = expf(v);
}

// -------- graph boundaries (batch is sorted): gstart[g] = lower_bound(g) ----
__global__ void k_gstart(void)
{
    int g = threadIdx.x;
    if (g > Gg) return;
    if (g == Gg) { g_gstart[g] = Nn; return; }
    int lo = 0, hi = Nn;
    while (lo < hi) {
        int mid = (lo + hi) >> 1;
        if (g_batch[mid] < g) lo = mid + 1; else hi = mid;
    }
    g_gstart[g] = lo;
}

// ---- GAT gather (row range [wbase, wbase+wcnt)): den summed inline ----------
__global__ __launch_bounds__(256) void k_gather(const __half* __restrict__ xp16,
                                                const float* __restrict__ bias,
                                                const float* __restrict__ ssrc,
                                                const float* __restrict__ sdst,
                                                __half* __restrict__ oh,
                                                int wbase, int wcnt)
{
    int wi = (blockIdx.x * blockDim.x + threadIdx.x) >> 5;
    int lane = threadIdx.x & 31;
    if (wi >= wcnt) return;
    int w = wbase + wi;
    int beg = g_offs[w], end = g_offs[w + 1];

    float vs = ssrc[w] + sdst[w];
    vs = vs > 0.f ? vs : NEG * vs;
    float ps = expf(vs);
    float den = ps;

    float acc[8];
    {
        uint4 rv = ((const uint4*)(xp16 + (size_t)w * Hd))[lane];
        float2 f0 = __half22float2(*(__half2*)&rv.x);
        float2 f1 = __half22float2(*(__half2*)&rv.y);
        float2 f2 = __half22float2(*(__half2*)&rv.z);
        float2 f3 = __half22float2(*(__half2*)&rv.w);
        acc[0] = ps * f0.x; acc[1] = ps * f0.y;
        acc[2] = ps * f1.x; acc[3] = ps * f1.y;
        acc[4] = ps * f2.x; acc[5] = ps * f2.y;
        acc[6] = ps * f3.x; acc[7] = ps * f3.y;
    }

    int i = beg;
    for (; i + 8 <= end; i += 8) {
        int   sI[8];
        float cI[8];
        #pragma unroll
        for (int q = 0; q < 8; q++) { sI[q] = g_adj[i + q]; cI[q] = g_p[i + q]; }
        uint4 rA[4], rB[4];
        #pragma unroll
        for (int q = 0; q < 4; q++)
            rA[q] = ((const uint4*)(xp16 + (size_t)sI[q] * Hd))[lane];
        #pragma unroll
        for (int q = 0; q < 4; q++)
            rB[q] = ((const uint4*)(xp16 + (size_t)sI[4 + q] * Hd))[lane];
        #pragma unroll
        for (int q = 0; q < 4; q++) {
            float cc = cI[q];
            den += cc;
            uint32_t* rw = (uint32_t*)&rA[q];
            #pragma unroll
            for (int h = 0; h < 4; h++) {
                float2 f = __half22float2(*(__half2*)&rw[h]);
                acc[h * 2]     = fmaf(cc, f.x, acc[h * 2]);
                acc[h * 2 + 1] = fmaf(cc, f.y, acc[h * 2 + 1]);
            }
        }
        #pragma unroll
        for (int q = 0; q < 4; q++) {
            float cc = cI[4 + q];
            den += cc;
            uint32_t* rw = (uint32_t*)&rB[q];
            #pragma unroll
            for (int h = 0; h < 4; h++) {
                float2 f = __half22float2(*(__half2*)&rw[h]);
                acc[h * 2]     = fmaf(cc, f.x, acc[h * 2]);
                acc[h * 2 + 1] = fmaf(cc, f.y, acc[h * 2 + 1]);
            }
        }
    }
    for (; i < end; i++) {
        int s = g_adj[i];
        float cc = g_p[i];
        den += cc;
        uint4 rv = ((const uint4*)(xp16 + (size_t)s * Hd))[lane];
        uint32_t* rw = (uint32_t*)&rv;
        #pragma unroll
        for (int h = 0; h < 4; h++) {
            float2 f = __half22float2(*(__half2*)&rw[h]);
            acc[h * 2]     = fmaf(cc, f.x, acc[h * 2]);
            acc[h * 2 + 1] = fmaf(cc, f.y, acc[h * 2 + 1]);
        }
    }

    float inv = 1.f / den;
    float4 b0 = ((const float4*)bias)[lane * 2];
    float4 b1 = ((const float4*)bias)[lane * 2 + 1];
    float bb[8] = {b0.x, b0.y, b0.z, b0.w, b1.x, b1.y, b1.z, b1.w};
    uint4 hs;
    uint32_t* hw = (uint32_t*)&hs;
    #pragma unroll
    for (int q = 0; q < 4; q++) {
        float v0 = fmaxf(fmaf(acc[q * 2], inv, bb[q * 2]), 0.f);
        float v1 = fmaxf(fmaf(acc[q * 2 + 1], inv, bb[q * 2 + 1]), 0.f);
        __half2 hh = __floats2half2_rn(v0, v1);
        hw[q] = *(uint32_t*)&hh;
    }
    *(uint4*)(oh + (size_t)w * Hd + 8 * lane) = hs;
}

// --------------- pooling: contiguous per-graph sum (batch sorted) -----------
__global__ __launch_bounds__(128) void k_pool_g(const float* __restrict__ hg,
                                                float* __restrict__ out)
{
    int g = blockIdx.x;
    int c = blockIdx.y * 128 + threadIdx.x;
    int beg = g_gstart[g], end = g_gstart[g + 1];
    float s = 0.f;
    for (int n = beg; n < end; n++) s += hg[(size_t)n * Hd + c];
    out[(size_t)g * (2 * Hd) + c] = s;
}

__global__ __launch_bounds__(256) void k_super(const float* __restrict__ Wf,
                                               const float* __restrict__ bf,
                                               float* __restrict__ out)
{
    __shared__ float s[Hd];
    int j = threadIdx.x;
    float sum = 0.f;
    for (int g = 0; g < Gg; g++) sum += out[(size_t)g * (2 * Hd) + j];
    s[j] = sum / (float)Gg;
    __syncthreads();
    float v = bf[j];
    #pragma unroll 8
    for (int c = 0; c < Hd; c++) v = fmaf(s[c], Wf[(size_t)j * Hd + c], v);
    v = fmaxf(v, 0.f);
    for (int g = 0; g < Gg; g++) out[(size_t)g * (2 * Hd) + Hd + j] = v;
}

// ------------------------------ launch --------------------------------------
extern "C" void kernel_launch(void* const* d_in, const int* in_sizes, int n_in,
                              void* d_out, int out_size)
{
    const float* x      = (const float*)d_in[0];
    const int*   ei32   = (const int*)d_in[1];
    const int*   b32    = (const int*)d_in[2];
    const float* W0     = (const float*)d_in[3];
    const float* a_src0 = (const float*)d_in[4];
    const float* a_dst0 = (const float*)d_in[5];
    const float* b0     = (const float*)d_in[6];
    const float* W1     = (const float*)d_in[7];
    const float* a_src1 = (const float*)d_in[8];
    const float* a_dst1 = (const float*)d_in[9];
    const float* b1     = (const float*)d_in[10];
    const float* W_ih   = (const float*)d_in[11];
    /* d_in[12] = W_hh: unused (h0 = 0) */
    const float* b_ih   = (const float*)d_in[13];
    const float* b_hh   = (const float*)d_in[14];
    const float* Wf     = (const float*)d_in[15];
    const float* bf     = (const float*)d_in[16];
    float*       out    = (float*)d_out;

    float *xp, *ssrc0, *sdst0, *ssrc1, *sdst1;
    __half *xp16, *ah, *bt0h, *bt1h, *bihh;
    cudaGetSymbolAddress((void**)&xp,    g_xp);
    cudaGetSymbolAddress((void**)&xp16,  g_xp16);
    cudaGetSymbolAddress((void**)&ssrc0, g_ssrc0);
    cudaGetSymbolAddress((void**)&sdst0, g_sdst0);
    cudaGetSymbolAddress((void**)&ssrc1, g_ssrc1);
    cudaGetSymbolAddress((void**)&sdst1, g_sdst1);
    cudaGetSymbolAddress((void**)&ah,    g_ah);
    cudaGetSymbolAddress((void**)&bt0h,  g_bt0h);
    cudaGetSymbolAddress((void**)&bt1h,  g_bt1h);
    cudaGetSymbolAddress((void**)&bihh,  g_bihh);

    const int SMEM  = 2 * BUF1;
    const int SMEMG = 2 * BUF1 + 2 * 128 * STSTR * 2;
    cudaFuncSetAttribute(k_mm_f16, cudaFuncAttributeMaxDynamicSharedMemorySize, SMEM);
    cudaFuncSetAttribute(k_mm_gru, cudaFuncAttributeMaxDynamicSharedMemorySize, SMEMG);

    // one-time side stream + events (resource init only)
    static cudaStream_t s2 = nullptr;
    static cudaEvent_t evF = nullptr, evJ = nullptr, eG0a = nullptr, eG0b = nullptr,
                       evE1 = nullptr, eG1a = nullptr, eG1b = nullptr, evJ2 = nullptr;
    if (s2 == nullptr) {
        cudaStreamCreateWithFlags(&s2, cudaStreamNonBlocking);
        cudaEventCreateWithFlags(&evF,  cudaEventDisableTiming);
        cudaEventCreateWithFlags(&evJ,  cudaEventDisableTiming);
        cudaEventCreateWithFlags(&eG0a, cudaEventDisableTiming);
        cudaEventCreateWithFlags(&eG0b, cudaEventDisableTiming);
        cudaEventCreateWithFlags(&evE1, cudaEventDisableTiming);
        cudaEventCreateWithFlags(&eG1a, cudaEventDisableTiming);
        cudaEventCreateWithFlags(&eG1b, cudaEventDisableTiming);
        cudaEventCreateWithFlags(&evJ2, cudaEventDisableTiming);
    }

    const int MT  = (Nn + 127) / 128;        // 391
    const int MT0 = HROW / 128;              // 196 tiles (rows 0..25088)
    const int MT1 = MT - MT0;                // 195 tiles
    const int W0N = HROW;                    // gather half 0: warps [0, 25088)
    const int W1N = Nn - HROW;               // gather half 1: warps [25088, 50000)
    dim3 blk(256);

    // ---- fork: CSR/decode branch on s2, weight/A-prep + L0 GEMM on main ----
    cudaEventRecord(evF, 0);
    cudaStreamWaitEvent(s2, evF, 0);

    // branch B (s2): index decode + CSR build + graph boundaries
    k_detect<<<1, 32, 0, s2>>>(ei32);
    k_decode_batch<<<(Nn + 255) / 256, blk, 0, s2>>>(b32);
    k_decode_count<<<(Ee + 255) / 256, blk, 0, s2>>>(ei32);
    k_scan_a<<<NSB, SCB, 0, s2>>>();
    k_scan_b<<<1, 128, 0, s2>>>();
    k_scan_c<<<NSB, SCB, 0, s2>>>();
    k_fill<<<(Ee + 255) / 256, blk, 0, s2>>>();
    k_gstart<<<1, Gg + 1, 0, s2>>>();
    cudaEventRecord(evJ, s2);

    // branch A (main): prep weights (+ zero scratch), convert x, L0 GEMM
    k_prep_w<<<(768 * 256 + 255) / 256, blk>>>(W0, W1, W_ih);
    k_split_x<<<(Nn * INC / 4 + 255) / 256, blk>>>(x, Nn * INC / 4);
    k_mm_f16<<<dim3(2, MT), blk, SMEM>>>(ah, bt0h, xp16,
                                         a_src0, a_dst0, ssrc0, sdst0, Nn, Hd, INC, 0);

    // ---- join: edge path needs CSR + L0 results ----
    cudaStreamWaitEvent(0, evJ, 0);

    // ---- GAT layer 0: edge weights + aggregate (halves) ----
    k_edgep<<<(Ee + 255) / 256, blk>>>(ssrc0, sdst0);
    k_gather<<<(W0N * 32 + 255) / 256, blk>>>(xp16, b0, ssrc0, sdst0, ah, 0, W0N);
    cudaEventRecord(eG0a, 0);
    k_gather<<<(W1N * 32 + 255) / 256, blk>>>(xp16, b0, ssrc0, sdst0, ah, HROW, W1N);
    cudaEventRecord(eG0b, 0);

    // ---- L1 GEMM halves on s2, overlapped with gather0(H1) ----
    cudaStreamWaitEvent(s2, eG0a, 0);
    k_mm_f16<<<dim3(2, MT0), blk, SMEM, s2>>>(ah, bt1h, xp16,
                                              a_src1, a_dst1, ssrc1, sdst1, Nn, Hd, Hd, 0);
    cudaStreamWaitEvent(s2, eG0b, 0);
    k_mm_f16<<<dim3(2, MT1), blk, SMEM, s2>>>(ah, bt1h, xp16,
                                              a_src1, a_dst1, ssrc1, sdst1, Nn, Hd, Hd, HROW);
    cudaEventRecord(evE1, s2);

    // ---- GAT layer 1 edge path (needs full L1) ----
    cudaStreamWaitEvent(0, evE1, 0);
    k_edgep<<<(Ee + 255) / 256, blk>>>(ssrc1, sdst1);
    k_gather<<<(W0N * 32 + 255) / 256, blk>>>(xp16, b1, ssrc1, sdst1, ah, 0, W0N);
    cudaEventRecord(eG1a, 0);
    k_gather<<<(W1N * 32 + 255) / 256, blk>>>(xp16, b1, ssrc1, sdst1, ah, HROW, W1N);
    cudaEventRecord(eG1b, 0);

    // ---- GRU halves on s2, overlapped with gather1(H1) ----
    cudaStreamWaitEvent(s2, eG1a, 0);
    k_mm_gru<<<dim3(2, MT0), blk, SMEMG, s2>>>(ah, bihh, b_ih, b_hh, xp, Nn, 0);
    cudaStreamWaitEvent(s2, eG1b, 0);
    k_mm_gru<<<dim3(2, MT1), blk, SMEMG, s2>>>(ah, bihh, b_ih, b_hh, xp, Nn, HROW);
    cudaEventRecord(evJ2, s2);

    // ---- pooling + super node ----
    cudaStreamWaitEvent(0, evJ2, 0);
    k_pool_g<<<dim3(Gg, 2), 128>>>(xp, out);
    k_super<<<1, Hd>>>(Wf, bf, out);
}